// round 12
// baseline (speedup 1.0000x reference)
#include <cuda_runtime.h>
#include <math.h>

// Problem constants (match reference)
#define T_STEPS 1024
#define B_SIZE  32768
#define G1      50
#define H1      32
#define G2      20
#define KAN_WARPS  8
#define KAN_BLOCKS (T_STEPS / KAN_WARPS)   // 128

// Scratch: dt * beta[t] (device global — no allocation allowed)
__device__ float g_cbeta[T_STEPS];

// ---------------------------------------------------------------------------
// Kernel 1: cbeta[t] = dt * softplus(KAN2(KAN1(t/T))).
// Warp-per-beta, fully warp-local, factorized layer-2 RBF (3 exps/(t,i)).
// PDL primary: completion (implicit trigger) releases the sir kernel's
// cudaGridDependencySynchronize with full memory visibility of g_cbeta.
// ---------------------------------------------------------------------------
__global__ void __launch_bounds__(256)
kan_beta_kernel(const float* __restrict__ t_steps,
                const float* __restrict__ grid1,
                const float* __restrict__ spline_w1, // [50,32]
                const float* __restrict__ base_w1,   // [32]
                const float* __restrict__ grid2,
                const float* __restrict__ spline_w2, // [32,20]
                const float* __restrict__ base_w2)   // [32]
{
    __shared__ float sbasis[KAN_WARPS][G1 + 2];
    __shared__ float sC2[KAN_WARPS][G2];

    const int w    = threadIdx.x >> 5;
    const int lane = threadIdx.x & 31;
    const int t    = blockIdx.x * KAN_WARPS + w;

    const float x  = t_steps[t];
    const float dt = t_steps[1] - t_steps[0];

    {   // layer-1 basis: 50 exps per warp
        float d = x - grid1[lane];
        sbasis[w][lane] = __expf(-10.0f * d * d);
        if (lane < G1 - 32) {
            float d2 = x - grid1[lane + 32];
            sbasis[w][lane + 32] = __expf(-10.0f * d2 * d2);
        }
    }
    if (lane < G2) {    // per-warp C2 table
        float v = grid2[lane] - 0.5f;
        sC2[w][lane] = __expf(-10.0f * v * v);
    }
    __syncwarp();

    // h[lane] = x*base_w1[lane] + sum_g basis[g]*w1[g][lane]
    float acc0 = x * base_w1[lane];
    float acc1 = 0.0f;
    #pragma unroll
    for (int g = 0; g < G1 - 1; g += 2) {
        acc0 = fmaf(sbasis[w][g],     spline_w1[g * H1 + lane],       acc0);
        acc1 = fmaf(sbasis[w][g + 1], spline_w1[(g + 1) * H1 + lane], acc1);
    }
    const float h = fmaf(sbasis[w][G1 - 1], spline_w1[(G1 - 1) * H1 + lane],
                         acc0 + acc1);

    // layer-2 factorized RBF: exp(-10(h-g_k)^2) = e0 * tk * C2[k]
    float u = fminf(fmaxf(h - 0.5f, -2.5f), 2.5f);   // clamp: basis ~0 there
    const float v0 = grid2[0] - 0.5f;
    const float dv = grid2[1] - grid2[0];
    const float e0 = __expf(-10.0f * u * u);
    float       tk = __expf(20.0f * u * v0);
    const float f  = __expf(20.0f * u * dv);

    float acc = 0.0f;
    #pragma unroll
    for (int k = 0; k < G2; k++) {
        acc = fmaf(tk * sC2[w][k], spline_w2[lane * G2 + k], acc);
        tk *= f;
    }
    acc = fmaf(h, base_w2[lane], e0 * acc);

    #pragma unroll
    for (int o = 16; o > 0; o >>= 1)
        acc += __shfl_down_sync(0xFFFFFFFFu, acc, o);

    if (lane == 0) {
        float beta = fmaxf(acc, 0.0f) + log1pf(expf(-fabsf(acc)));  // softplus
        g_cbeta[t] = dt * beta;
    }
}

// ---------------------------------------------------------------------------
// Kernel 2: Euler SIR scan (PDL secondary). Launches concurrently with kan;
// does all beta-independent work first, then cudaGridDependencySynchronize()
// (waits for kan completion, with guaranteed visibility of g_cbeta), then
// loads betas and runs the DRAM-write-bound 24.5us scan.
// ---------------------------------------------------------------------------
__global__ void __launch_bounds__(64)
sir_scan_kernel(const float* __restrict__ initial_I,
                const float* __restrict__ t_steps,
                const float* __restrict__ gamma_param,
                float* __restrict__ out)
{
    __shared__ float scb[T_STEPS + 8];   // padded: t+1 prefetch never guards

    // ---- Beta-independent prologue (overlaps kan execution) ----
    const int b = blockIdx.x * 64 + threadIdx.x;
    const float I_init = initial_I[b];
    const float gp     = gamma_param[0];
    const float dt     = t_steps[1] - t_steps[0];
    const float gamma  = fmaxf(gp, 0.0f) + log1pf(expf(-fabsf(gp)));
    const float a      = 1.0f - dt * gamma;   // I' = I*a + ni

    // ---- Wait for kan (PDL dependency) ----
    cudaGridDependencySynchronize();

    #pragma unroll
    for (int i = 0; i < T_STEPS / 64; i++)
        scb[threadIdx.x + i * 64] = g_cbeta[threadIdx.x + i * 64];
    if (threadIdx.x < 8) scb[T_STEPS + threadIdx.x] = 0.0f;

    float I = I_init;
    float S = 1.0f - I;

    __syncthreads();

    float* outp = out + b;
    float cb = scb[0];
    #pragma unroll 8
    for (int t = 0; t < T_STEPS; t++) {
        const float cb_n = scb[t + 1];       // prefetch next beta
        const float ni = cb * (S * I);       // dt * new_infections
        I = fmaf(I, a, ni);                  // clips removed: state in [0,1]
        S = S - ni;
        outp[(size_t)t * B_SIZE] = I;
        cb = cb_n;
    }
}

// ---------------------------------------------------------------------------
// Inputs (metadata order):
// 0: t_steps [1024], 1: initial_I [32768], 2: grid1 [50], 3: spline_w1 [1600],
// 4: base_w1 [32], 5: grid2 [20], 6: spline_w2 [640], 7: base_w2 [32],
// 8: gamma_param [1]
// ---------------------------------------------------------------------------
extern "C" void kernel_launch(void* const* d_in, const int* in_sizes, int n_in,
                              void* d_out, int out_size)
{
    const float* t_steps    = (const float*)d_in[0];
    const float* initial_I  = (const float*)d_in[1];
    const float* grid1      = (const float*)d_in[2];
    const float* spline_w1  = (const float*)d_in[3];
    const float* base_w1    = (const float*)d_in[4];
    const float* grid2      = (const float*)d_in[5];
    const float* spline_w2  = (const float*)d_in[6];
    const float* base_w2    = (const float*)d_in[7];
    const float* gamma_p    = (const float*)d_in[8];
    float* out              = (float*)d_out;

    kan_beta_kernel<<<KAN_BLOCKS, 256>>>(t_steps, grid1, spline_w1, base_w1,
                                         grid2, spline_w2, base_w2);

    // PDL secondary launch: overlaps with kan, syncs in-kernel.
    cudaLaunchConfig_t cfg = {};
    cfg.gridDim  = dim3(B_SIZE / 64, 1, 1);
    cfg.blockDim = dim3(64, 1, 1);
    cfg.dynamicSmemBytes = 0;
    cfg.stream = 0;
    cudaLaunchAttribute attrs[1];
    attrs[0].id = cudaLaunchAttributeProgrammaticStreamSerialization;
    attrs[0].val.programmaticStreamSerializationAllowed = 1;
    cfg.attrs = attrs;
    cfg.numAttrs = 1;
    cudaLaunchKernelEx(&cfg, sir_scan_kernel, initial_I, t_steps, gamma_p, out);
}

// round 13
// speedup vs baseline: 1.0569x; 1.0569x over previous
#include <cuda_runtime.h>
#include <math.h>

// Problem constants (match reference)
#define T_STEPS 1024
#define B_SIZE  32768
#define G1      50
#define H1      32
#define G2      20

#define KAN_BLOCKS 256                  // producer blocks (dispatched first)
#define SIR_BLOCKS 512                  // consumer blocks
#define NBLOCKS    (KAN_BLOCKS + SIR_BLOCKS)

// Device globals (zero-init at load; NEVER reset — monotonic across launches)
__device__ float        g_cbeta[T_STEPS];
__device__ unsigned int g_cnt;                       // producer arrivals
__device__ unsigned int g_blkepoch[SIR_BLOCKS];      // per-consumer epoch

// ---------------------------------------------------------------------------
// Single-kernel role split.
//  Blocks 0..255 (producers, dispatched first): each warp computes 2 betas
//    (factorized layer-2 RBF, warp-local), then tid0 fences and RED-arrives
//    on g_cnt (atomicAdd, return unused -> REDG, 0.854 cyc/op: no ALU storm).
//  Blocks 256..767 (consumers): bump own epoch e (owner-only, race-free),
//    run beta-independent prologue, spin until g_cnt >= 256*e (monotonic
//    target: stale counter from launch N-1 = 256(e-1) can never pass),
//    then the proven DRAM-write-bound 24.5us Euler scan.
// Deadlock safety: 768 blocks x 64 thr = ~5.2 blocks/SM -> whole grid is
// resident in one wave; producers are low-bid (dispatched first). Consumers
// spin only on producers, never on other consumers.
// ---------------------------------------------------------------------------
__global__ void __launch_bounds__(64)
fused_role_kernel(const float* __restrict__ t_steps,
                  const float* __restrict__ initial_I,
                  const float* __restrict__ grid1,
                  const float* __restrict__ spline_w1, // [50,32]
                  const float* __restrict__ base_w1,   // [32]
                  const float* __restrict__ grid2,
                  const float* __restrict__ spline_w2, // [32,20]
                  const float* __restrict__ base_w2,   // [32]
                  const float* __restrict__ gamma_param,
                  float* __restrict__ out)
{
    __shared__ float smem_f[T_STEPS + 8];   // sir: beta cache | kan: scratch

    const int tid  = threadIdx.x;
    const int w    = tid >> 5;
    const int lane = tid & 31;

    if (blockIdx.x < KAN_BLOCKS) {
        // =================== PRODUCER: 4 betas per block ===================
        float* basis = &smem_f[w * 64];          // per-warp 50-float slice
        float* C2w   = &smem_f[128 + w * 32];    // per-warp 20-float slice

        // C2[k] = exp(-10*(grid2[k]-0.5)^2)
        if (lane < G2) {
            float v = grid2[lane] - 0.5f;
            C2w[lane] = __expf(-10.0f * v * v);
        }

        const float dt = t_steps[1] - t_steps[0];

        #pragma unroll
        for (int s = 0; s < 2; s++) {
            const int   t = blockIdx.x * 4 + w * 2 + s;
            const float x = t_steps[t];

            // layer-1 basis: 50 exps (lanes 0..17 do two)
            {
                float d = x - grid1[lane];
                basis[lane] = __expf(-10.0f * d * d);
                if (lane < G1 - 32) {
                    float d2 = x - grid1[lane + 32];
                    basis[lane + 32] = __expf(-10.0f * d2 * d2);
                }
            }
            __syncwarp();

            // h[lane] = x*base_w1[lane] + sum_g basis[g]*w1[g][lane]
            float h = x * base_w1[lane];
            #pragma unroll
            for (int g = 0; g < G1; g++)
                h = fmaf(basis[g], spline_w1[g * H1 + lane], h);

            // layer-2 factorized RBF: exp(-10(h-g_k)^2) = e0 * tk * C2[k]
            float u = fminf(fmaxf(h - 0.5f, -2.5f), 2.5f); // clamp: basis ~0
            const float v0 = grid2[0] - 0.5f;
            const float dv = grid2[1] - grid2[0];
            const float e0 = __expf(-10.0f * u * u);
            float       tk = __expf(20.0f * u * v0);
            const float f  = __expf(20.0f * u * dv);

            float acc = 0.0f;
            #pragma unroll
            for (int k = 0; k < G2; k++) {
                acc = fmaf(tk * C2w[k], spline_w2[lane * G2 + k], acc);
                tk *= f;
            }
            acc = fmaf(h, base_w2[lane], e0 * acc);

            #pragma unroll
            for (int o = 16; o > 0; o >>= 1)
                acc += __shfl_down_sync(0xFFFFFFFFu, acc, o);

            if (lane == 0) {
                float beta = fmaxf(acc, 0.0f) + log1pf(expf(-fabsf(acc)));
                g_cbeta[t] = dt * beta;
            }
            __syncwarp();
        }

        __syncthreads();
        if (tid == 0) {
            __threadfence();               // publish betas before arrival
            atomicAdd(&g_cnt, 1u);         // return unused -> REDG
        }
        return;
    }

    // ===================== CONSUMER: Euler SIR scan ======================
    const int sbid = blockIdx.x - KAN_BLOCKS;

    __shared__ unsigned int starget;
    if (tid == 0) {
        unsigned int e = g_blkepoch[sbid] + 1u;   // owner-only, race-free
        g_blkepoch[sbid] = e;
        starget = e * KAN_BLOCKS;                 // monotonic counter target
    }

    // Beta-independent prologue (overlaps producers)
    const int   b      = sbid * 64 + tid;
    const float I_init = initial_I[b];
    const float gp     = gamma_param[0];
    const float dt     = t_steps[1] - t_steps[0];
    const float gamma  = fmaxf(gp, 0.0f) + log1pf(expf(-fabsf(gp)));
    const float a      = 1.0f - dt * gamma;       // I' = I*a + ni

    __syncthreads();                              // starget visible
    if (tid == 0) {
        const unsigned int tgt = starget;
        while (*((volatile unsigned int*)&g_cnt) < tgt) { }
        __threadfence();                          // acquire betas
    }
    __syncthreads();

    #pragma unroll
    for (int i = 0; i < T_STEPS / 64; i++)
        smem_f[tid + i * 64] = __ldcg(&g_cbeta[tid + i * 64]);
    if (tid < 8) smem_f[T_STEPS + tid] = 0.0f;    // prefetch sentinel

    float I = I_init;
    float S = 1.0f - I;

    __syncthreads();

    float* outp = out + b;
    float cb = smem_f[0];
    #pragma unroll 8
    for (int t = 0; t < T_STEPS; t++) {
        const float cb_n = smem_f[t + 1];         // prefetch next beta
        const float ni = cb * (S * I);            // dt * new_infections
        I = fmaf(I, a, ni);                       // clips removed: state in [0,1]
        S = S - ni;
        outp[(size_t)t * B_SIZE] = I;
        cb = cb_n;
    }
}

// ---------------------------------------------------------------------------
// Inputs (metadata order):
// 0: t_steps [1024], 1: initial_I [32768], 2: grid1 [50], 3: spline_w1 [1600],
// 4: base_w1 [32], 5: grid2 [20], 6: spline_w2 [640], 7: base_w2 [32],
// 8: gamma_param [1]
// ---------------------------------------------------------------------------
extern "C" void kernel_launch(void* const* d_in, const int* in_sizes, int n_in,
                              void* d_out, int out_size)
{
    const float* t_steps    = (const float*)d_in[0];
    const float* initial_I  = (const float*)d_in[1];
    const float* grid1      = (const float*)d_in[2];
    const float* spline_w1  = (const float*)d_in[3];
    const float* base_w1    = (const float*)d_in[4];
    const float* grid2      = (const float*)d_in[5];
    const float* spline_w2  = (const float*)d_in[6];
    const float* base_w2    = (const float*)d_in[7];
    const float* gamma_p    = (const float*)d_in[8];
    float* out              = (float*)d_out;

    fused_role_kernel<<<NBLOCKS, 64>>>(t_steps, initial_I, grid1,
                                       spline_w1, base_w1, grid2,
                                       spline_w2, base_w2, gamma_p, out);
}